// round 1
// baseline (speedup 1.0000x reference)
#include <cuda_runtime.h>
#include <float.h>

// Problem shape (fixed by the dataset)
#define BB    32
#define LL    8192
#define DD    256
#define TOPK  8
#define CHUNK 512
#define SS    (LL / CHUNK)     // 16 chunks along L
#define GRP   4                // row-groups per chunk (tid/64)
#define SUB   (CHUNK / GRP)    // 128 rows per group

// Scratch (device globals: no allocation allowed in kernel_launch)
__device__ int   g_len[BB];
__device__ float g_part[(size_t)BB * SS * GRP * DD * TOPK];  // 16.8 MB

// Sorted-descending top-8 insert; array must live in registers (fully unrolled use).
__device__ __forceinline__ void ins8(float (&v)[TOPK], float x) {
    if (x > v[TOPK - 1]) {
        v[TOPK - 1] = x;
        #pragma unroll
        for (int j = TOPK - 1; j >= 1; --j) {
            if (v[j] > v[j - 1]) { float t = v[j - 1]; v[j - 1] = v[j]; v[j] = t; }
        }
    }
}

// ---------------------------------------------------------------------------
// Kernel 0: valid length per batch. mask is 1 on padded positions and is
// monotone (arange >= length) by the reference's construction, so
// len = L - sum(mask) and the valid region is [0, len).
// ---------------------------------------------------------------------------
__global__ void len_kernel(const int* __restrict__ mask) {
    int b = blockIdx.x;
    int t = threadIdx.x;
    const int* m = mask + (size_t)b * LL;
    int sum = 0;
    for (int i = t; i < LL; i += 256) sum += m[i];
    __shared__ int sh[256];
    sh[t] = sum;
    __syncthreads();
    #pragma unroll
    for (int o = 128; o > 0; o >>= 1) {
        if (t < o) sh[t] += sh[t + o];
        __syncthreads();
    }
    if (t == 0) g_len[b] = LL - sh[0];
}

// ---------------------------------------------------------------------------
// Kernel 1: per-chunk partial top-8.
// Block = (chunk s, batch b), 256 threads.
// Thread: q = tid&63 -> channels [4q, 4q+4); g = tid>>6 -> rows
// [s*CHUNK + g*SUB, +SUB) clipped to len. float4 loads: a warp reads 512B
// contiguous per row. Each thread keeps 4 register-resident sorted top-8s.
// ---------------------------------------------------------------------------
__global__ __launch_bounds__(256) void partial_kernel(const float* __restrict__ x) {
    int b   = blockIdx.y;
    int s   = blockIdx.x;
    int tid = threadIdx.x;
    int q   = tid & 63;
    int g   = tid >> 6;

    int len = g_len[b];
    int lo  = s * CHUNK + g * SUB;
    int hi  = min(lo + SUB, len);

    float v[GRP][TOPK];
    #pragma unroll
    for (int c = 0; c < GRP; ++c)
        #pragma unroll
        for (int j = 0; j < TOPK; ++j) v[c][j] = -FLT_MAX;

    const float4* p = reinterpret_cast<const float4*>(
                          x + (size_t)b * LL * DD + (size_t)lo * DD) + q;
    #pragma unroll 4
    for (int l = lo; l < hi; ++l, p += DD / 4) {
        float4 xv = __ldg(p);
        ins8(v[0], xv.x);
        ins8(v[1], xv.y);
        ins8(v[2], xv.z);
        ins8(v[3], xv.w);
    }

    // 128B contiguous per thread, contiguous across threads -> coalesced.
    float* dst = g_part + ((((size_t)b * SS + s) * GRP + g) * DD + (size_t)q * 4) * TOPK;
    #pragma unroll
    for (int c = 0; c < 4; ++c)
        #pragma unroll
        for (int j = 0; j < TOPK; ++j) dst[c * TOPK + j] = v[c][j];
}

// ---------------------------------------------------------------------------
// Kernel 2: merge 64 sorted partial top-8s per (b, d) and write output.
// out[b, k*D + d] = k-th largest. Writes coalesced over d.
// ---------------------------------------------------------------------------
__global__ __launch_bounds__(DD) void merge_kernel(float* __restrict__ out) {
    int b = blockIdx.x;
    int d = threadIdx.x;

    float v[TOPK];
    #pragma unroll
    for (int j = 0; j < TOPK; ++j) v[j] = -FLT_MAX;

    const float* base = g_part + ((size_t)b * SS * GRP * DD + d) * TOPK;
    for (int p = 0; p < SS * GRP; ++p) {
        const float4* c4 = reinterpret_cast<const float4*>(base + (size_t)p * DD * TOPK);
        float4 a = __ldg(c4);
        float4 bq = __ldg(c4 + 1);
        ins8(v, a.x); ins8(v, a.y); ins8(v, a.z); ins8(v, a.w);
        ins8(v, bq.x); ins8(v, bq.y); ins8(v, bq.z); ins8(v, bq.w);
    }

    #pragma unroll
    for (int k = 0; k < TOPK; ++k)
        out[(size_t)b * TOPK * DD + (size_t)k * DD + d] = v[k];
}

extern "C" void kernel_launch(void* const* d_in, const int* in_sizes, int n_in,
                              void* d_out, int out_size) {
    const float* x    = (const float*)d_in[0];
    const int*   mask = (const int*)d_in[1];
    float*       out  = (float*)d_out;

    len_kernel<<<BB, 256>>>(mask);
    partial_kernel<<<dim3(SS, BB), 256>>>(x);
    merge_kernel<<<BB, DD>>>(out);
}

// round 2
// speedup vs baseline: 1.8961x; 1.8961x over previous
#include <cuda_runtime.h>
#include <float.h>

// Problem shape (fixed by the dataset)
#define BB    32
#define LL    8192
#define DD    256
#define TOPK  8
#define CHUNK 256
#define SS    (LL / CHUNK)     // 32 chunks along L
#define GRP   4                // row-groups per chunk (tid>>6)
#define SUB   (CHUNK / GRP)    // 64 rows per group
#define PART  (SS * GRP)       // 128 partials per (b, d) column

// Scratch (device globals: no allocation allowed anywhere)
__device__ int   g_len[BB];
__device__ float g_part[(size_t)BB * PART * DD * TOPK];  // 33.5 MB

#define NEG (-FLT_MAX)

// Compare-exchange, descending (a keeps max). 2 FMNMX, no branches.
#define CE(a, b) { float _hi = fmaxf(a, b); float _lo = fminf(a, b); (a) = _hi; (b) = _lo; }

// ---------------------------------------------------------------------------
// Branchless exact top-8 update with 4 new values.
// Invariant: v[0..7] sorted descending on entry and exit.
// sort-4 (5 CE) + sorted-partner max (4 ops) + bitonic merge-8 (12 CE).
// Partner step: top8(V ∪ S) as a multiset = { max(v[i], s_desc[7-i]) } for
// sorted-descending V, S (S padded with -inf). Result is bitonic -> merge.
// ---------------------------------------------------------------------------
__device__ __forceinline__ void upd8(float (&v)[TOPK],
                                     float a0, float a1, float a2, float a3) {
    // sort 4 descending
    CE(a0, a1); CE(a2, a3); CE(a0, a2); CE(a1, a3); CE(a1, a2);
    // partner max against tail
    v[4] = fmaxf(v[4], a3);
    v[5] = fmaxf(v[5], a2);
    v[6] = fmaxf(v[6], a1);
    v[7] = fmaxf(v[7], a0);
    // bitonic merge to descending
    CE(v[0], v[4]); CE(v[1], v[5]); CE(v[2], v[6]); CE(v[3], v[7]);
    CE(v[0], v[2]); CE(v[1], v[3]); CE(v[4], v[6]); CE(v[5], v[7]);
    CE(v[0], v[1]); CE(v[2], v[3]); CE(v[4], v[5]); CE(v[6], v[7]);
}

// Merge a full sorted-descending 8-list s into v (both sorted desc).
__device__ __forceinline__ void merge8(float (&v)[TOPK], const float (&s)[TOPK]) {
    v[0] = fmaxf(v[0], s[7]); v[1] = fmaxf(v[1], s[6]);
    v[2] = fmaxf(v[2], s[5]); v[3] = fmaxf(v[3], s[4]);
    v[4] = fmaxf(v[4], s[3]); v[5] = fmaxf(v[5], s[2]);
    v[6] = fmaxf(v[6], s[1]); v[7] = fmaxf(v[7], s[0]);
    CE(v[0], v[4]); CE(v[1], v[5]); CE(v[2], v[6]); CE(v[3], v[7]);
    CE(v[0], v[2]); CE(v[1], v[3]); CE(v[4], v[6]); CE(v[5], v[7]);
    CE(v[0], v[1]); CE(v[2], v[3]); CE(v[4], v[5]); CE(v[6], v[7]);
}

// ---------------------------------------------------------------------------
// Kernel 0: valid length per batch via transition search. mask is monotone
// (0...0 1...1) by construction: len = first index of 1 (or L if none).
// Exactly one thread writes per batch -> no init, no atomics, deterministic.
// ---------------------------------------------------------------------------
__global__ void len_kernel(const int* __restrict__ mask) {
    int b  = blockIdx.y;
    int lo = blockIdx.x * (LL / 8);
    const int* m = mask + (size_t)b * LL;
    for (int i = lo + threadIdx.x; i < lo + LL / 8; i += 256) {
        int mi = m[i];
        if (i == LL - 1) {
            if (mi == 0) g_len[b] = LL;
        } else if (mi == 0 && m[i + 1] == 1) {
            g_len[b] = i + 1;
        }
    }
}

// ---------------------------------------------------------------------------
// Kernel 1: per-chunk branchless partial top-8.
// Block = (chunk s, batch b). Thread: q = tid&63 -> channels [4q,4q+4),
// g = tid>>6 -> rows [s*CHUNK + g*SUB, +SUB) clipped to len.
// float4 loads: 64 consecutive threads read 1KB contiguous per row.
// ---------------------------------------------------------------------------
__global__ __launch_bounds__(256) void partial_kernel(const float* __restrict__ x) {
    int b   = blockIdx.y;
    int s   = blockIdx.x;
    int tid = threadIdx.x;
    int q   = tid & 63;
    int g   = tid >> 6;

    int len = g_len[b];
    int lo  = s * CHUNK + g * SUB;
    int hi  = min(lo + SUB, len);
    int nrows = hi - lo;            // may be <= 0

    float v0[TOPK], v1[TOPK], v2[TOPK], v3[TOPK];
    #pragma unroll
    for (int j = 0; j < TOPK; ++j) { v0[j] = NEG; v1[j] = NEG; v2[j] = NEG; v3[j] = NEG; }

    const float4* p = reinterpret_cast<const float4*>(
                          x + (size_t)b * LL * DD + (size_t)lo * DD) + q;

    int nfull = nrows >> 2;
    #pragma unroll 2
    for (int it = 0; it < nfull; ++it) {
        float4 r0 = __ldcs(p);
        float4 r1 = __ldcs(p + DD / 4);
        float4 r2 = __ldcs(p + 2 * (DD / 4));
        float4 r3 = __ldcs(p + 3 * (DD / 4));
        p += DD;  // 4 rows
        upd8(v0, r0.x, r1.x, r2.x, r3.x);
        upd8(v1, r0.y, r1.y, r2.y, r3.y);
        upd8(v2, r0.z, r1.z, r2.z, r3.z);
        upd8(v3, r0.w, r1.w, r2.w, r3.w);
    }
    int rem = nrows > 0 ? (nrows & 3) : 0;
    if (rem) {
        float4 pad = make_float4(NEG, NEG, NEG, NEG);
        float4 r0 = __ldcs(p);
        float4 r1 = (rem > 1) ? __ldcs(p + DD / 4) : pad;
        float4 r2 = (rem > 2) ? __ldcs(p + 2 * (DD / 4)) : pad;
        upd8(v0, r0.x, r1.x, r2.x, NEG);
        upd8(v1, r0.y, r1.y, r2.y, NEG);
        upd8(v2, r0.z, r1.z, r2.z, NEG);
        upd8(v3, r0.w, r1.w, r2.w, NEG);
    }

    // store 4 sorted lists: 128B contiguous per thread, coalesced across threads
    int part = s * GRP + g;
    float* dst = g_part + (((size_t)b * PART + part) * DD + (size_t)q * 4) * TOPK;
    #pragma unroll
    for (int j = 0; j < TOPK; ++j) dst[0 * TOPK + j] = v0[j];
    #pragma unroll
    for (int j = 0; j < TOPK; ++j) dst[1 * TOPK + j] = v1[j];
    #pragma unroll
    for (int j = 0; j < TOPK; ++j) dst[2 * TOPK + j] = v2[j];
    #pragma unroll
    for (int j = 0; j < TOPK; ++j) dst[3 * TOPK + j] = v3[j];
}

// ---------------------------------------------------------------------------
// Kernel 2: merge 128 sorted partial 8-lists per (b, d).
// 512 threads: d = tid&255, h = tid>>8 each merge 64 partials (coalesced
// 32B/thread loads), halves combined through smem, lower half writes out.
// ---------------------------------------------------------------------------
__global__ __launch_bounds__(512) void merge_kernel(float* __restrict__ out) {
    __shared__ float sh[DD][TOPK];
    int b = blockIdx.x;
    int d = threadIdx.x & (DD - 1);
    int h = threadIdx.x >> 8;

    float v[TOPK];
    #pragma unroll
    for (int j = 0; j < TOPK; ++j) v[j] = NEG;

    const float* base = g_part + (((size_t)b * PART + (size_t)h * (PART / 2)) * DD + d) * TOPK;
    #pragma unroll 4
    for (int p = 0; p < PART / 2; ++p) {
        const float4* c4 = reinterpret_cast<const float4*>(base + (size_t)p * DD * TOPK);
        float4 a = __ldg(c4);
        float4 c = __ldg(c4 + 1);
        float s[TOPK] = {a.x, a.y, a.z, a.w, c.x, c.y, c.z, c.w};  // sorted desc
        merge8(v, s);
    }

    if (h == 1) {
        #pragma unroll
        for (int j = 0; j < TOPK; ++j) sh[d][j] = v[j];
    }
    __syncthreads();
    if (h == 0) {
        float s[TOPK];
        #pragma unroll
        for (int j = 0; j < TOPK; ++j) s[j] = sh[d][j];
        merge8(v, s);
        #pragma unroll
        for (int k = 0; k < TOPK; ++k)
            out[(size_t)b * TOPK * DD + (size_t)k * DD + d] = v[k];
    }
}

extern "C" void kernel_launch(void* const* d_in, const int* in_sizes, int n_in,
                              void* d_out, int out_size) {
    const float* x    = (const float*)d_in[0];
    const int*   mask = (const int*)d_in[1];
    float*       out  = (float*)d_out;

    len_kernel<<<dim3(8, BB), 256>>>(mask);
    partial_kernel<<<dim3(SS, BB), 256>>>(x);
    merge_kernel<<<BB, 512>>>(out);
}

// round 3
// speedup vs baseline: 3.7224x; 1.9632x over previous
#include <cuda_runtime.h>
#include <float.h>

// Problem shape (fixed by the dataset)
#define BB    32
#define LL    8192
#define DD    256
#define TOPK  8
#define CHUNK 256
#define SS    (LL / CHUNK)     // 32 chunks along L
#define GRP   4                // row-groups per chunk (tid>>6)
#define SUB   (CHUNK / GRP)    // 64 rows per group

// Scratch (device globals: no allocation allowed anywhere)
__device__ float g_part[(size_t)BB * SS * DD * TOPK];  // 8.4 MB

#define NEG (-FLT_MAX)

// Compare-exchange, descending (a keeps max). 2 FMNMX, no branches.
#define CE(a, b) { float _hi = fmaxf(a, b); float _lo = fminf(a, b); (a) = _hi; (b) = _lo; }

// Batcher odd-even sort-8, descending. 19 CE = 38 ops, depth 6.
__device__ __forceinline__ void sort8(float (&s)[8]) {
    CE(s[0], s[1]); CE(s[2], s[3]); CE(s[4], s[5]); CE(s[6], s[7]);
    CE(s[0], s[2]); CE(s[1], s[3]); CE(s[4], s[6]); CE(s[5], s[7]);
    CE(s[1], s[2]); CE(s[5], s[6]);
    CE(s[0], s[4]); CE(s[1], s[5]); CE(s[2], s[6]); CE(s[3], s[7]);
    CE(s[2], s[4]); CE(s[3], s[5]);
    CE(s[1], s[2]); CE(s[3], s[4]); CE(s[5], s[6]);
}

// Merge sorted-desc 8-list s into sorted-desc accumulator v (exact top-8 of
// the union). Partner stage = first stage of the bitonic merge of v·rev(s)
// (a bitonic-16), whose top half contains the top-8 and is bitonic; then a
// 3-stage bitonic merge-8 restores descending order. 8 + 24 = 32 ops.
__device__ __forceinline__ void acc8(float (&v)[8], const float (&s)[8]) {
    v[0] = fmaxf(v[0], s[7]); v[1] = fmaxf(v[1], s[6]);
    v[2] = fmaxf(v[2], s[5]); v[3] = fmaxf(v[3], s[4]);
    v[4] = fmaxf(v[4], s[3]); v[5] = fmaxf(v[5], s[2]);
    v[6] = fmaxf(v[6], s[1]); v[7] = fmaxf(v[7], s[0]);
    CE(v[0], v[4]); CE(v[1], v[5]); CE(v[2], v[6]); CE(v[3], v[7]);
    CE(v[0], v[2]); CE(v[1], v[3]); CE(v[4], v[6]); CE(v[5], v[7]);
    CE(v[0], v[1]); CE(v[2], v[3]); CE(v[4], v[5]); CE(v[6], v[7]);
}

// ---------------------------------------------------------------------------
// Kernel 1: per-chunk top-8, self-contained (reads its own mask slice).
// Block = (chunk s, batch b), 256 threads. q = tid&63 -> channels [4q,4q+4),
// g = tid>>6 -> rows [g*SUB, (g+1)*SUB) of the chunk, clipped by nvalid.
// 8-row batches: sort8 per channel + merge into register accumulator.
// Group results combined through smem; one sorted 8-list per (chunk, channel)
// written to scratch (coalesced 8KB per block).
// ---------------------------------------------------------------------------
__global__ __launch_bounds__(256) void partial_kernel(const float* __restrict__ x,
                                                      const int* __restrict__ mask) {
    __shared__ float sh[GRP][DD][TOPK + 1];   // +1 pad: conflict-free
    __shared__ int   wcnt[8];

    int b   = blockIdx.y;
    int s   = blockIdx.x;
    int tid = threadIdx.x;
    int q   = tid & 63;
    int g   = tid >> 6;
    int lo  = s * CHUNK;

    // nvalid for this chunk from its own mask rows (monotone 0...0 1...1)
    int m = mask[(size_t)b * LL + lo + tid];
    unsigned bal = __ballot_sync(0xffffffffu, m == 0);
    if ((tid & 31) == 0) wcnt[tid >> 5] = __popc(bal);
    __syncthreads();
    int nvalid = 0;
    #pragma unroll
    for (int w = 0; w < 8; ++w) nvalid += wcnt[w];

    float* dst = g_part + (((size_t)b * SS + s) * DD + tid) * TOPK;
    if (nvalid == 0) {   // fully padded chunk: still must define its scratch
        #pragma unroll
        for (int j = 0; j < TOPK; ++j) dst[j] = NEG;
        return;
    }

    int nv = min(max(nvalid - g * SUB, 0), SUB);
    int nfull = nv >> 3;
    int rem   = nv & 7;

    float v0[8], v1[8], v2[8], v3[8];
    #pragma unroll
    for (int j = 0; j < 8; ++j) { v0[j] = NEG; v1[j] = NEG; v2[j] = NEG; v3[j] = NEG; }

    const float4* p = reinterpret_cast<const float4*>(
                          x + ((size_t)b * LL + lo + g * SUB) * DD) + q;

    #pragma unroll 1
    for (int it = 0; it < nfull; ++it) {
        float4 r[8];
        #pragma unroll
        for (int j = 0; j < 8; ++j) r[j] = __ldcs(p + j * (DD / 4));
        p += 8 * (DD / 4);
        float t[8];
        #pragma unroll
        for (int j = 0; j < 8; ++j) t[j] = r[j].x;
        sort8(t); acc8(v0, t);
        #pragma unroll
        for (int j = 0; j < 8; ++j) t[j] = r[j].y;
        sort8(t); acc8(v1, t);
        #pragma unroll
        for (int j = 0; j < 8; ++j) t[j] = r[j].z;
        sort8(t); acc8(v2, t);
        #pragma unroll
        for (int j = 0; j < 8; ++j) t[j] = r[j].w;
        sort8(t); acc8(v3, t);
    }
    if (rem) {   // warp-uniform branch (g is uniform per warp)
        float4 r[8];
        #pragma unroll
        for (int j = 0; j < 8; ++j) r[j] = __ldcs(p + j * (DD / 4));  // in-bounds (within chunk)
        float t[8];
        #pragma unroll
        for (int j = 0; j < 8; ++j) t[j] = (j < rem) ? r[j].x : NEG;
        sort8(t); acc8(v0, t);
        #pragma unroll
        for (int j = 0; j < 8; ++j) t[j] = (j < rem) ? r[j].y : NEG;
        sort8(t); acc8(v1, t);
        #pragma unroll
        for (int j = 0; j < 8; ++j) t[j] = (j < rem) ? r[j].z : NEG;
        sort8(t); acc8(v2, t);
        #pragma unroll
        for (int j = 0; j < 8; ++j) t[j] = (j < rem) ? r[j].w : NEG;
        sort8(t); acc8(v3, t);
    }

    // combine the 4 row-groups per channel through smem
    #pragma unroll
    for (int j = 0; j < 8; ++j) sh[g][4 * q + 0][j] = v0[j];
    #pragma unroll
    for (int j = 0; j < 8; ++j) sh[g][4 * q + 1][j] = v1[j];
    #pragma unroll
    for (int j = 0; j < 8; ++j) sh[g][4 * q + 2][j] = v2[j];
    #pragma unroll
    for (int j = 0; j < 8; ++j) sh[g][4 * q + 3][j] = v3[j];
    __syncthreads();

    int d = tid;   // one channel per thread
    float v[8];
    #pragma unroll
    for (int j = 0; j < 8; ++j) v[j] = sh[0][d][j];
    #pragma unroll
    for (int gg = 1; gg < GRP; ++gg) {
        float t[8];
        #pragma unroll
        for (int j = 0; j < 8; ++j) t[j] = sh[gg][d][j];
        acc8(v, t);
    }
    #pragma unroll
    for (int j = 0; j < TOPK; ++j) dst[j] = v[j];   // 32B/thread, coalesced
}

// ---------------------------------------------------------------------------
// Kernel 2: merge the 32 sorted chunk-lists per (b, d) and write output.
// Thread d reads 32B per chunk (block reads 8KB contiguous per chunk).
// ---------------------------------------------------------------------------
__global__ __launch_bounds__(DD) void merge_kernel(float* __restrict__ out) {
    int b = blockIdx.x;
    int d = threadIdx.x;

    float v[8];
    #pragma unroll
    for (int j = 0; j < 8; ++j) v[j] = NEG;

    const float* base = g_part + ((size_t)b * SS * DD + d) * TOPK;
    #pragma unroll 4
    for (int p = 0; p < SS; ++p) {
        const float4* c4 = reinterpret_cast<const float4*>(base + (size_t)p * DD * TOPK);
        float4 a = __ldg(c4);
        float4 c = __ldg(c4 + 1);
        float t[8] = {a.x, a.y, a.z, a.w, c.x, c.y, c.z, c.w};  // sorted desc
        acc8(v, t);
    }

    #pragma unroll
    for (int k = 0; k < TOPK; ++k)
        out[(size_t)b * TOPK * DD + (size_t)k * DD + d] = v[k];
}

extern "C" void kernel_launch(void* const* d_in, const int* in_sizes, int n_in,
                              void* d_out, int out_size) {
    const float* x    = (const float*)d_in[0];
    const int*   mask = (const int*)d_in[1];
    float*       out  = (float*)d_out;

    partial_kernel<<<dim3(SS, BB), 256>>>(x, mask);
    merge_kernel<<<BB, DD>>>(out);
}

// round 4
// speedup vs baseline: 4.1276x; 1.1088x over previous
#include <cuda_runtime.h>
#include <float.h>

// Problem shape (fixed by the dataset)
#define BB    32
#define LL    8192
#define DD    256
#define TOPK  8
#define CHUNK 256
#define SS    (LL / CHUNK)     // 32 chunks along L
#define GRP   4                // row-groups per chunk (tid>>6)
#define SUB   (CHUNK / GRP)    // 64 rows per group

// Scratch (device globals: no allocation allowed anywhere)
__device__ float g_part[(size_t)BB * SS * DD * TOPK];  // 8.4 MB

#define NEG (-FLT_MAX)

// Compare-exchange, descending (a keeps max). 2 FMNMX, no branches.
#define CE(a, b) { float _hi = fmaxf(a, b); float _lo = fminf(a, b); (a) = _hi; (b) = _lo; }

// Batcher odd-even sort-8, descending. 19 CE = 38 ops (optimal CE count).
__device__ __forceinline__ void sort8(float (&s)[8]) {
    CE(s[0], s[1]); CE(s[2], s[3]); CE(s[4], s[5]); CE(s[6], s[7]);
    CE(s[0], s[2]); CE(s[1], s[3]); CE(s[4], s[6]); CE(s[5], s[7]);
    CE(s[1], s[2]); CE(s[5], s[6]);
    CE(s[0], s[4]); CE(s[1], s[5]); CE(s[2], s[6]); CE(s[3], s[7]);
    CE(s[2], s[4]); CE(s[3], s[5]);
    CE(s[1], s[2]); CE(s[3], s[4]); CE(s[5], s[6]);
}

// Merge sorted-desc 8-list s into sorted-desc accumulator v (exact top-8 of
// the union). Partner stage (8 ops) + 3-stage bitonic merge-8 (24 ops).
__device__ __forceinline__ void acc8(float (&v)[8], const float (&s)[8]) {
    v[0] = fmaxf(v[0], s[7]); v[1] = fmaxf(v[1], s[6]);
    v[2] = fmaxf(v[2], s[5]); v[3] = fmaxf(v[3], s[4]);
    v[4] = fmaxf(v[4], s[3]); v[5] = fmaxf(v[5], s[2]);
    v[6] = fmaxf(v[6], s[1]); v[7] = fmaxf(v[7], s[0]);
    CE(v[0], v[4]); CE(v[1], v[5]); CE(v[2], v[6]); CE(v[3], v[7]);
    CE(v[0], v[2]); CE(v[1], v[3]); CE(v[4], v[6]); CE(v[5], v[7]);
    CE(v[0], v[1]); CE(v[2], v[3]); CE(v[4], v[5]); CE(v[6], v[7]);
}

// ---------------------------------------------------------------------------
// Kernel 1: per-chunk top-8, self-contained (reads its own mask slice).
// Block = (chunk s, batch b), 256 threads. q = tid&63 -> channels [4q,4q+4),
// g = tid>>6 -> rows [g*SUB, (g+1)*SUB) of the chunk, clipped by nvalid.
// 8-row batches: sort8 per channel + merge into register accumulator.
// Group results combined through smem; one sorted 8-list per (chunk, channel)
// written to scratch (coalesced 8KB per block).
// ---------------------------------------------------------------------------
__global__ __launch_bounds__(256) void partial_kernel(const float* __restrict__ x,
                                                      const int* __restrict__ mask) {
    __shared__ float sh[GRP][DD][TOPK + 1];   // +1 pad: conflict-free
    __shared__ int   wcnt[8];

    int b   = blockIdx.y;
    int s   = blockIdx.x;
    int tid = threadIdx.x;
    int q   = tid & 63;
    int g   = tid >> 6;
    int lo  = s * CHUNK;

    // nvalid for this chunk from its own mask rows (monotone 0...0 1...1)
    int m = mask[(size_t)b * LL + lo + tid];
    unsigned bal = __ballot_sync(0xffffffffu, m == 0);
    if ((tid & 31) == 0) wcnt[tid >> 5] = __popc(bal);
    __syncthreads();
    int nvalid = 0;
    #pragma unroll
    for (int w = 0; w < 8; ++w) nvalid += wcnt[w];

    float* dst = g_part + (((size_t)b * SS + s) * DD + tid) * TOPK;
    if (nvalid == 0) {   // fully padded chunk: still must define its scratch
        #pragma unroll
        for (int j = 0; j < TOPK; ++j) dst[j] = NEG;
        return;
    }

    int nv = min(max(nvalid - g * SUB, 0), SUB);
    int nfull = nv >> 3;
    int rem   = nv & 7;

    float v0[8], v1[8], v2[8], v3[8];
    #pragma unroll
    for (int j = 0; j < 8; ++j) { v0[j] = NEG; v1[j] = NEG; v2[j] = NEG; v3[j] = NEG; }

    const float4* p = reinterpret_cast<const float4*>(
                          x + ((size_t)b * LL + lo + g * SUB) * DD) + q;

    #pragma unroll 1
    for (int it = 0; it < nfull; ++it) {
        float4 r[8];
        #pragma unroll
        for (int j = 0; j < 8; ++j) r[j] = __ldcs(p + j * (DD / 4));
        p += 8 * (DD / 4);
        float t[8];
        #pragma unroll
        for (int j = 0; j < 8; ++j) t[j] = r[j].x;
        sort8(t); acc8(v0, t);
        #pragma unroll
        for (int j = 0; j < 8; ++j) t[j] = r[j].y;
        sort8(t); acc8(v1, t);
        #pragma unroll
        for (int j = 0; j < 8; ++j) t[j] = r[j].z;
        sort8(t); acc8(v2, t);
        #pragma unroll
        for (int j = 0; j < 8; ++j) t[j] = r[j].w;
        sort8(t); acc8(v3, t);
    }
    if (rem) {   // warp-uniform branch (g is uniform per warp)
        float4 r[8];
        #pragma unroll
        for (int j = 0; j < 8; ++j) r[j] = __ldcs(p + j * (DD / 4));  // in-bounds (within chunk)
        float t[8];
        #pragma unroll
        for (int j = 0; j < 8; ++j) t[j] = (j < rem) ? r[j].x : NEG;
        sort8(t); acc8(v0, t);
        #pragma unroll
        for (int j = 0; j < 8; ++j) t[j] = (j < rem) ? r[j].y : NEG;
        sort8(t); acc8(v1, t);
        #pragma unroll
        for (int j = 0; j < 8; ++j) t[j] = (j < rem) ? r[j].z : NEG;
        sort8(t); acc8(v2, t);
        #pragma unroll
        for (int j = 0; j < 8; ++j) t[j] = (j < rem) ? r[j].w : NEG;
        sort8(t); acc8(v3, t);
    }

    // combine the 4 row-groups per channel through smem
    #pragma unroll
    for (int j = 0; j < 8; ++j) sh[g][4 * q + 0][j] = v0[j];
    #pragma unroll
    for (int j = 0; j < 8; ++j) sh[g][4 * q + 1][j] = v1[j];
    #pragma unroll
    for (int j = 0; j < 8; ++j) sh[g][4 * q + 2][j] = v2[j];
    #pragma unroll
    for (int j = 0; j < 8; ++j) sh[g][4 * q + 3][j] = v3[j];
    __syncthreads();

    int d = tid;   // one channel per thread
    float v[8];
    #pragma unroll
    for (int j = 0; j < 8; ++j) v[j] = sh[0][d][j];
    #pragma unroll
    for (int gg = 1; gg < GRP; ++gg) {
        float t[8];
        #pragma unroll
        for (int j = 0; j < 8; ++j) t[j] = sh[gg][d][j];
        acc8(v, t);
    }
    #pragma unroll
    for (int j = 0; j < TOPK; ++j) dst[j] = v[j];   // 32B/thread, coalesced
}

// ---------------------------------------------------------------------------
// Kernel 2: merge the 32 sorted chunk-lists per (b, d).
// Grid (BB, 2), 512 threads: block covers 128 channels; c = tid&127 is the
// channel within the block, seg = tid>>7 in [0,4) owns 8 chunks. 64 blocks,
// 1024 warps, per-thread chain of 8 iterations with 2 independent LDG.128.
// Segment results combined through smem; seg 0 writes the output.
// ---------------------------------------------------------------------------
__global__ __launch_bounds__(512) void merge_kernel(float* __restrict__ out) {
    __shared__ float sh[3][128][TOPK + 1];   // +1 pad: conflict-free
    int b    = blockIdx.x;
    int half = blockIdx.y;
    int c    = threadIdx.x & 127;
    int seg  = threadIdx.x >> 7;             // 0..3
    int d    = half * 128 + c;

    const float* base = g_part + ((size_t)b * SS * DD + d) * TOPK;

    // Seed from this segment's first chunk (lists are sorted desc already).
    const float4* c0 = reinterpret_cast<const float4*>(base + (size_t)(seg * 8) * DD * TOPK);
    float4 a0 = __ldg(c0);
    float4 b0 = __ldg(c0 + 1);
    float v[8] = {a0.x, a0.y, a0.z, a0.w, b0.x, b0.y, b0.z, b0.w};

    #pragma unroll
    for (int p = 1; p < 8; ++p) {
        const float4* c4 = reinterpret_cast<const float4*>(
            base + (size_t)(seg * 8 + p) * DD * TOPK);
        float4 a = __ldg(c4);
        float4 e = __ldg(c4 + 1);
        float t[8] = {a.x, a.y, a.z, a.w, e.x, e.y, e.z, e.w};
        acc8(v, t);
    }

    if (seg) {
        #pragma unroll
        for (int j = 0; j < 8; ++j) sh[seg - 1][c][j] = v[j];
    }
    __syncthreads();
    if (seg == 0) {
        #pragma unroll
        for (int ss = 0; ss < 3; ++ss) {
            float t[8];
            #pragma unroll
            for (int j = 0; j < 8; ++j) t[j] = sh[ss][c][j];
            acc8(v, t);
        }
        #pragma unroll
        for (int k = 0; k < TOPK; ++k)
            out[(size_t)b * TOPK * DD + (size_t)k * DD + d] = v[k];
    }
}

extern "C" void kernel_launch(void* const* d_in, const int* in_sizes, int n_in,
                              void* d_out, int out_size) {
    const float* x    = (const float*)d_in[0];
    const int*   mask = (const int*)d_in[1];
    float*       out  = (float*)d_out;

    partial_kernel<<<dim3(SS, BB), 256>>>(x, mask);
    merge_kernel<<<dim3(BB, 2), 512>>>(out);
}

// round 5
// speedup vs baseline: 4.4007x; 1.0662x over previous
#include <cuda_runtime.h>
#include <float.h>

// Problem shape (fixed by the dataset)
#define BB    32
#define LL    8192
#define DD    256
#define TOPK  8
#define CHUNK 256
#define SS    (LL / CHUNK)     // 32 chunks along L
#define GRP   4                // row-groups per chunk (tid>>6)
#define SUB   (CHUNK / GRP)    // 64 rows per group

// Scratch (device globals: no allocation allowed anywhere)
__device__ float g_part[(size_t)BB * SS * DD * TOPK];  // 8.4 MB
__device__ int   g_nchunk[BB];                         // valid chunks per batch

#define NEG (-FLT_MAX)

// Compare-exchange, descending (a keeps max). 2 FMNMX, no branches.
#define CE(a, b) { float _hi = fmaxf(a, b); float _lo = fminf(a, b); (a) = _hi; (b) = _lo; }

// Batcher odd-even sort-8, descending. 19 CE = 38 ops (optimal CE count).
__device__ __forceinline__ void sort8(float (&s)[8]) {
    CE(s[0], s[1]); CE(s[2], s[3]); CE(s[4], s[5]); CE(s[6], s[7]);
    CE(s[0], s[2]); CE(s[1], s[3]); CE(s[4], s[6]); CE(s[5], s[7]);
    CE(s[1], s[2]); CE(s[5], s[6]);
    CE(s[0], s[4]); CE(s[1], s[5]); CE(s[2], s[6]); CE(s[3], s[7]);
    CE(s[2], s[4]); CE(s[3], s[5]);
    CE(s[1], s[2]); CE(s[3], s[4]); CE(s[5], s[6]);
}

// Merge sorted-desc 8-list s into sorted-desc accumulator v (exact top-8 of
// the union). Partner stage (8 ops) + 3-stage bitonic merge-8 (24 ops).
__device__ __forceinline__ void acc8(float (&v)[8], const float (&s)[8]) {
    v[0] = fmaxf(v[0], s[7]); v[1] = fmaxf(v[1], s[6]);
    v[2] = fmaxf(v[2], s[5]); v[3] = fmaxf(v[3], s[4]);
    v[4] = fmaxf(v[4], s[3]); v[5] = fmaxf(v[5], s[2]);
    v[6] = fmaxf(v[6], s[1]); v[7] = fmaxf(v[7], s[0]);
    CE(v[0], v[4]); CE(v[1], v[5]); CE(v[2], v[6]); CE(v[3], v[7]);
    CE(v[0], v[2]); CE(v[1], v[3]); CE(v[4], v[6]); CE(v[5], v[7]);
    CE(v[0], v[1]); CE(v[2], v[3]); CE(v[4], v[5]); CE(v[6], v[7]);
}

// ---------------------------------------------------------------------------
// Kernel 1: per-chunk top-8, self-contained (reads its own mask slice).
// Block = (chunk s, batch b), 256 threads. q = tid&63 -> channels [4q,4q+4),
// g = tid>>6 -> rows [g*SUB, (g+1)*SUB) of the chunk, clipped by nvalid.
// The unique boundary block publishes g_nchunk[b]; fully padded chunks exit
// without storing (merge never reads them).
// ---------------------------------------------------------------------------
__global__ __launch_bounds__(256) void partial_kernel(const float* __restrict__ x,
                                                      const int* __restrict__ mask) {
    __shared__ float sh[GRP][DD][TOPK + 1];   // +1 pad: conflict-free
    __shared__ int   wcnt[8];

    int b   = blockIdx.y;
    int s   = blockIdx.x;
    int tid = threadIdx.x;
    int q   = tid & 63;
    int g   = tid >> 6;
    int lo  = s * CHUNK;

    // nvalid for this chunk from its own mask rows (monotone 0...0 1...1)
    int m = mask[(size_t)b * LL + lo + tid];
    unsigned bal = __ballot_sync(0xffffffffu, m == 0);
    if ((tid & 31) == 0) wcnt[tid >> 5] = __popc(bal);
    __syncthreads();
    int nvalid = 0;
    #pragma unroll
    for (int w = 0; w < 8; ++w) nvalid += wcnt[w];

    // Publish the valid-chunk count: exactly one block per batch qualifies.
    if (tid == 0 && nvalid > 0) {
        bool last;
        if (nvalid < CHUNK)      last = true;
        else if (s == SS - 1)    last = true;
        else                     last = (mask[(size_t)b * LL + lo + CHUNK] == 1);
        if (last) g_nchunk[b] = s + 1;
    }
    if (nvalid == 0) return;   // merge never reads this chunk

    int nv = min(max(nvalid - g * SUB, 0), SUB);
    int nfull = nv >> 3;
    int rem   = nv & 7;

    float v0[8], v1[8], v2[8], v3[8];
    #pragma unroll
    for (int j = 0; j < 8; ++j) { v0[j] = NEG; v1[j] = NEG; v2[j] = NEG; v3[j] = NEG; }

    const float4* p = reinterpret_cast<const float4*>(
                          x + ((size_t)b * LL + lo + g * SUB) * DD) + q;

    #pragma unroll 1
    for (int it = 0; it < nfull; ++it) {
        float4 r[8];
        #pragma unroll
        for (int j = 0; j < 8; ++j) r[j] = __ldcs(p + j * (DD / 4));
        p += 8 * (DD / 4);
        float t[8];
        #pragma unroll
        for (int j = 0; j < 8; ++j) t[j] = r[j].x;
        sort8(t); acc8(v0, t);
        #pragma unroll
        for (int j = 0; j < 8; ++j) t[j] = r[j].y;
        sort8(t); acc8(v1, t);
        #pragma unroll
        for (int j = 0; j < 8; ++j) t[j] = r[j].z;
        sort8(t); acc8(v2, t);
        #pragma unroll
        for (int j = 0; j < 8; ++j) t[j] = r[j].w;
        sort8(t); acc8(v3, t);
    }
    if (rem) {   // warp-uniform branch (g is uniform per warp)
        float4 r[8];
        #pragma unroll
        for (int j = 0; j < 8; ++j) r[j] = __ldcs(p + j * (DD / 4));  // in-bounds (within chunk)
        float t[8];
        #pragma unroll
        for (int j = 0; j < 8; ++j) t[j] = (j < rem) ? r[j].x : NEG;
        sort8(t); acc8(v0, t);
        #pragma unroll
        for (int j = 0; j < 8; ++j) t[j] = (j < rem) ? r[j].y : NEG;
        sort8(t); acc8(v1, t);
        #pragma unroll
        for (int j = 0; j < 8; ++j) t[j] = (j < rem) ? r[j].z : NEG;
        sort8(t); acc8(v2, t);
        #pragma unroll
        for (int j = 0; j < 8; ++j) t[j] = (j < rem) ? r[j].w : NEG;
        sort8(t); acc8(v3, t);
    }

    // combine the 4 row-groups per channel through smem
    #pragma unroll
    for (int j = 0; j < 8; ++j) sh[g][4 * q + 0][j] = v0[j];
    #pragma unroll
    for (int j = 0; j < 8; ++j) sh[g][4 * q + 1][j] = v1[j];
    #pragma unroll
    for (int j = 0; j < 8; ++j) sh[g][4 * q + 2][j] = v2[j];
    #pragma unroll
    for (int j = 0; j < 8; ++j) sh[g][4 * q + 3][j] = v3[j];
    __syncthreads();

    int d = tid;   // one channel per thread
    float v[8];
    #pragma unroll
    for (int j = 0; j < 8; ++j) v[j] = sh[0][d][j];
    #pragma unroll
    for (int gg = 1; gg < GRP; ++gg) {
        float t[8];
        #pragma unroll
        for (int j = 0; j < 8; ++j) t[j] = sh[gg][d][j];
        acc8(v, t);
    }
    float* dst = g_part + (((size_t)b * SS + s) * DD + tid) * TOPK;
    #pragma unroll
    for (int j = 0; j < TOPK; ++j) dst[j] = v[j];   // 32B/thread, coalesced
}

// ---------------------------------------------------------------------------
// Kernel 2: merge the nc valid sorted chunk-lists per (b, d).
// Grid (BB, 8), 256 threads: block covers 32 channels (c = tid&31);
// seg = tid>>5 in [0,8) owns chunks [4*seg, 4*seg+4) clipped to nc.
// 256 blocks x 8 warps = 2048 warps; per-thread chain <= 4 iterations.
// Segment results combined through smem; seg 0 writes the output.
// ---------------------------------------------------------------------------
__global__ __launch_bounds__(256) void merge_kernel(float* __restrict__ out) {
    __shared__ float sh[7][32][TOPK + 1];   // +1 pad: conflict-free
    int b   = blockIdx.x;
    int grp = blockIdx.y;                   // channel group of 32
    int c   = threadIdx.x & 31;
    int seg = threadIdx.x >> 5;             // 0..7
    int d   = grp * 32 + c;

    int nc = g_nchunk[b];                   // valid chunks, 1..32
    int p0 = seg * 4;
    int p1 = min(p0 + 4, nc);

    const float* base = g_part + ((size_t)b * SS * DD + d) * TOPK;

    float v[8];
    #pragma unroll
    for (int j = 0; j < 8; ++j) v[j] = NEG;

    for (int p = p0; p < p1; ++p) {
        const float4* c4 = reinterpret_cast<const float4*>(base + (size_t)p * DD * TOPK);
        float4 a = __ldg(c4);
        float4 e = __ldg(c4 + 1);
        float t[8] = {a.x, a.y, a.z, a.w, e.x, e.y, e.z, e.w};  // sorted desc
        acc8(v, t);
    }

    if (seg) {
        #pragma unroll
        for (int j = 0; j < 8; ++j) sh[seg - 1][c][j] = v[j];
    }
    __syncthreads();
    if (seg == 0) {
        #pragma unroll
        for (int ss = 0; ss < 7; ++ss) {
            float t[8];
            #pragma unroll
            for (int j = 0; j < 8; ++j) t[j] = sh[ss][c][j];
            acc8(v, t);
        }
        #pragma unroll
        for (int k = 0; k < TOPK; ++k)
            out[(size_t)b * TOPK * DD + (size_t)k * DD + d] = v[k];
    }
}

extern "C" void kernel_launch(void* const* d_in, const int* in_sizes, int n_in,
                              void* d_out, int out_size) {
    const float* x    = (const float*)d_in[0];
    const int*   mask = (const int*)d_in[1];
    float*       out  = (float*)d_out;

    partial_kernel<<<dim3(SS, BB), 256>>>(x, mask);
    merge_kernel<<<dim3(BB, 8), 256>>>(out);
}